// round 13
// baseline (speedup 1.0000x reference)
#include <cuda_runtime.h>
#include <math.h>

#define SEQ 20
#define H   128
#define NC  100000

// ---------------- device scratch (no allocations allowed) ----------------
__device__ float g_comb[SEQ][2*H];        // [fwd_h, bwd_h] from rec1
__device__ float g_hl[SEQ][2*H];          // layer-2 hidden states from rec2

// ---------------- helpers ----------------
__device__ __forceinline__ void fma2(unsigned long long& d,
                                     unsigned long long a, unsigned long long b) {
    asm("fma.rn.f32x2 %0, %1, %2, %0;" : "+l"(d) : "l"(a), "l"(b));
}
__device__ __forceinline__ float sum2(unsigned long long v) {
    float lo, hi;
    asm("mov.b64 {%0, %1}, %2;" : "=f"(lo), "=f"(hi) : "l"(v));
    return lo + hi;
}
__device__ __forceinline__ float sigm(float x) { return 1.0f / (1.0f + expf(-x)); }

__device__ __forceinline__ unsigned smem_u32(const void* p) {
    return (unsigned)__cvta_generic_to_shared(p);
}
__device__ __forceinline__ unsigned mapa_u32(unsigned addr, unsigned rank) {
    unsigned d;
    asm("mapa.shared::cluster.u32 %0, %1, %2;" : "=r"(d) : "r"(addr), "r"(rank));
    return d;
}
__device__ __forceinline__ unsigned ctarank() {
    unsigned r; asm("mov.u32 %0, %%cluster_ctarank;" : "=r"(r)); return r;
}
#define CLUSTER_SYNC() do { \
    asm volatile("barrier.cluster.arrive.aligned;" ::: "memory"); \
    asm volatile("barrier.cluster.wait.aligned;"   ::: "memory"); } while (0)

// ---- st.async + mbarrier tx sync ----
__device__ __forceinline__ void mbar_init(unsigned addr, unsigned count) {
    asm volatile("mbarrier.init.shared.b64 [%0], %1;" :: "r"(addr), "r"(count) : "memory");
}
__device__ __forceinline__ void mbar_expect(unsigned addr, unsigned bytes) {
    asm volatile("mbarrier.arrive.expect_tx.shared.b64 _, [%0], %1;"
                 :: "r"(addr), "r"(bytes) : "memory");
}
__device__ __forceinline__ void mbar_wait(unsigned addr, unsigned parity) {
    asm volatile(
        "{\n\t"
        ".reg .pred P;\n\t"
        "LW%=:\n\t"
        "mbarrier.try_wait.parity.acquire.cluster.shared::cta.b64 P, [%0], %1, 0x989680;\n\t"
        "@P bra LD%=;\n\t"
        "bra LW%=;\n\t"
        "LD%=:\n\t"
        "}"
        :: "r"(addr), "r"(parity) : "memory");
}
__device__ __forceinline__ void st_async_b64(unsigned raddr, unsigned long long v, unsigned rmbar) {
    asm volatile("st.async.shared::cluster.mbarrier::complete_tx::bytes.b64 [%0], %1, [%2];"
                 :: "r"(raddr), "l"(v), "r"(rmbar) : "memory");
}

__device__ __forceinline__ void cp16(unsigned dst, const float* src) {
    asm volatile("cp.async.cg.shared.global [%0], [%1], 16;" :: "r"(dst), "l"(src));
}
__device__ __forceinline__ void cp_commit() {
    asm volatile("cp.async.commit_group;" ::: "memory");
}
__device__ __forceinline__ void cp_wait1() {
    asm volatile("cp.async.wait_group 1;" ::: "memory");
}
__device__ __forceinline__ void cp_wait0() {
    asm volatile("cp.async.wait_group 0;" ::: "memory");
}

// =====================================================================
// gemm_kernel<K>: head GEMM. out[t][n] = sum_k A[t][k]*W[n][k] + b[n].
// 4n x 5t register tile, cp.async double-buffered W streaming.
// A is read from g_hl.
// =====================================================================
template<int K>
__device__ __forceinline__ void issue_chunk(unsigned bufu, const float* __restrict__ W,
                                            long nbase, int N, int ch, int tid) {
    #pragma unroll
    for (int i = 0; i < 16; i++) {
        int idx = i * 128 + tid;
        int r = idx >> 4, c4 = idx & 15;
        long n = nbase + r; if (n >= N) n = 0;
        cp16(bufu + (unsigned)(r * 68 + c4 * 4) * 4u,
             W + n * K + ch * 64 + c4 * 4);
    }
    cp_commit();
}

template<int K>
__global__ void gemm_kernel(const float* __restrict__ W,
                            const float* __restrict__ b1,
                            float* __restrict__ out,
                            int N)
{
    constexpr int NCH = K / 64;
    extern __shared__ float sm[];
    float* sB0 = sm;                       // 128 * 68
    float* sB1 = sm + 128 * 68;
    float* sA  = sm + 2 * 128 * 68;        // SEQ * K

    const int tid = threadIdx.x;           // 128
    long nbase = (long)blockIdx.x * 128;

    unsigned b0u = smem_u32(sB0), b1u = smem_u32(sB1);
    issue_chunk<K>(b0u, W, nbase, N, 0, tid);
    if (NCH > 1) issue_chunk<K>(b1u, W, nbase, N, 1, tid);

    const float* A = &g_hl[0][0];
    for (int idx = tid; idx < SEQ * (K / 4); idx += 128)
        reinterpret_cast<float4*>(sA)[idx] = reinterpret_cast<const float4*>(A)[idx];

    const int lane = tid & 31;
    const int tg   = tid >> 5;
    const int t0   = tg * 5;

    unsigned long long acc[20];
    #pragma unroll
    for (int i = 0; i < 20; i++) acc[i] = 0ull;

    #pragma unroll 1
    for (int ch = 0; ch < NCH; ch++) {
        if (ch < NCH - 1) cp_wait1(); else cp_wait0();
        __syncthreads();
        const float* buf = (ch & 1) ? sB1 : sB0;

        #pragma unroll
        for (int k4 = 0; k4 < 16; k4++) {
            ulonglong2 w[4], a[5];
            #pragma unroll
            for (int i = 0; i < 4; i++)
                w[i] = *reinterpret_cast<const ulonglong2*>(&buf[(lane + 32 * i) * 68 + 4 * k4]);
            #pragma unroll
            for (int j = 0; j < 5; j++)
                a[j] = *reinterpret_cast<const ulonglong2*>(&sA[(t0 + j) * K + ch * 64 + 4 * k4]);
            #pragma unroll
            for (int i = 0; i < 4; i++)
                #pragma unroll
                for (int j = 0; j < 5; j++) {
                    fma2(acc[i * 5 + j], w[i].x, a[j].x);
                    fma2(acc[i * 5 + j], w[i].y, a[j].y);
                }
        }
        __syncthreads();
        if (ch + 2 < NCH)
            issue_chunk<K>((ch & 1) ? b1u : b0u, W, nbase, N, ch + 2, tid);
    }

    #pragma unroll
    for (int i = 0; i < 4; i++) {
        long n = nbase + lane + 32 * i;
        if (n < N) {
            float bias = b1[n];
            #pragma unroll
            for (int j = 0; j < 5; j++)
                out[(long)(t0 + j) * N + n] = sum2(acc[i * 5 + j]) + bias;
        }
    }
}

// =====================================================================
// rec1 (FUSED): layer-1 LSTM incl. its own x-projection.
// 2 clusters of 4 CTAs (grid 8), 256 threads. Thread pair (2m,2m+1)
// owns gate row m (k-halves of 64). Prologue computes the 20-step
// x-projection for own rows from x + Wih (register row halves).
// Main loop: Whh in registers, h exchanged via packed st.async.b64,
// mbarrier tx-wait as the only per-step sync.
// =====================================================================
__global__ void __cluster_dims__(4, 1, 1) __launch_bounds__(256, 1)
rec1_kernel(const float* __restrict__ x,
            const float* __restrict__ Wih_f, const float* __restrict__ Whh_f,
            const float* __restrict__ bih_f, const float* __restrict__ bhh_f,
            const float* __restrict__ Wih_b, const float* __restrict__ Whh_b,
            const float* __restrict__ bih_b, const float* __restrict__ bhh_b,
            const float* __restrict__ h0f, const float* __restrict__ c0f,
            const float* __restrict__ h0b, const float* __restrict__ c0b)
{
    __shared__ float sxin[SEQ * H];          // staged x (reversed for bwd)
    __shared__ float sX[SEQ * 128];          // x-proj addends for own rows
    __shared__ __align__(16) float sh[2][H];
    __shared__ float sg[128];
    __shared__ float sc[32];
    __shared__ __align__(8) unsigned long long mbar[2];

    const int tid = threadIdx.x;             // 256
    const unsigned s = ctarank();            // 0..3
    const int d  = blockIdx.x >> 2;
    const int j0 = (int)s * 32;

    const float* Wih = d ? Wih_b : Wih_f;
    const float* Whh = d ? Whh_b : Whh_f;
    const float* bih = d ? bih_b : bih_f;
    const float* bhh = d ? bhh_b : bhh_f;
    const float* h0  = d ? h0b : h0f;
    const float* c0  = d ? c0b : c0f;

    const int rr = tid >> 1;                          // local gate row 0..127
    const int kh = (tid & 1) * 64;                    // k half
    const int grow = ((rr >> 5) << 7) + j0 + (rr & 31);
    const float bias = bih[grow] + bhh[grow];

    // ---- prologue: stage x, compute own-row x-projection ----
    for (int idx = tid; idx < SEQ * H; idx += 256) {
        int t = idx >> 7, k = idx & 127;
        sxin[idx] = d ? x[(SEQ - 1 - t) * H + k] : x[idx];
    }
    {
        unsigned long long wi[32];
        const ulonglong2* wg = reinterpret_cast<const ulonglong2*>(Wih + (long)grow * H + kh);
        #pragma unroll
        for (int i = 0; i < 16; i++) { ulonglong2 v = wg[i]; wi[2*i] = v.x; wi[2*i+1] = v.y; }
        __syncthreads();
        #pragma unroll 1
        for (int t = 0; t < SEQ; t++) {
            unsigned long long a0 = 0ull, a1 = 0ull;
            const float* xv = &sxin[t * H + kh];
            #pragma unroll
            for (int i = 0; i < 16; i++) {
                ulonglong2 h2 = *reinterpret_cast<const ulonglong2*>(xv + 4 * i);
                fma2(a0, wi[2*i],   h2.x);
                fma2(a1, wi[2*i+1], h2.y);
            }
            float part = sum2(a0) + sum2(a1);
            part += __shfl_xor_sync(0xffffffffu, part, 1);
            if (!(tid & 1)) sX[t * 128 + rr] = part + bias;
        }
    }

    // ---- Whh half row -> registers ----
    unsigned long long w[32];
    {
        const ulonglong2* wg = reinterpret_cast<const ulonglong2*>(Whh + (long)grow * H + kh);
        #pragma unroll
        for (int i = 0; i < 16; i++) { ulonglong2 v = wg[i]; w[2*i] = v.x; w[2*i+1] = v.y; }
    }
    if (tid < H)  sh[0][tid] = h0[tid];
    if (tid < 32) sc[tid]    = c0[j0 + tid];
    if (tid == 0) { mbar_init(smem_u32(&mbar[0]), 1); mbar_init(smem_u32(&mbar[1]), 1); }
    __syncthreads();
    CLUSTER_SYNC();                           // mbar init + sX visible

    int ph0 = 0, ph1 = 0;
    #pragma unroll 1
    for (int t = 0; t < SEQ; t++) {
        if (t > 0) {
            int b = t & 1;
            mbar_wait(smem_u32(&mbar[b]), b ? ph1 : ph0);
            if (b) ph1 ^= 1; else ph0 ^= 1;
        }
        if (tid == 0 && t + 1 < SEQ) mbar_expect(smem_u32(&mbar[(t+1) & 1]), 4 * 32 * 4);

        const float* hb = sh[t & 1];
        unsigned long long a0 = 0ull, a1 = 0ull;
        #pragma unroll
        for (int i = 0; i < 16; i++) {
            ulonglong2 h2 = *reinterpret_cast<const ulonglong2*>(&hb[kh + 4 * i]);
            fma2(a0, w[2*i],   h2.x);
            fma2(a1, w[2*i+1], h2.y);
        }
        float part = sum2(a0) + sum2(a1);
        part += __shfl_xor_sync(0xffffffffu, part, 1);
        if (!(tid & 1)) sg[rr] = part + sX[t * 128 + rr];
        __syncthreads();

        if (tid < 32) {
            float gi = sg[tid], gf = sg[32 + tid], gg = sg[64 + tid], go = sg[96 + tid];
            float c = sigm(gf) * sc[tid] + sigm(gi) * tanhf(gg);
            float h = sigm(go) * tanhf(c);
            sc[tid] = c;
            g_comb[t][d * H + j0 + tid] = h;  // bwd kept in reversed-scan order
            if (t + 1 < SEQ) {
                float hn = __shfl_down_sync(0xffffffffu, h, 1);
                if (!(tid & 1)) {
                    unsigned long long pv;
                    asm("mov.b64 %0, {%1, %2};" : "=l"(pv) : "f"(h), "f"(hn));
                    unsigned la = smem_u32(&sh[(t+1) & 1][j0 + tid]);
                    unsigned lm = smem_u32(&mbar[(t+1) & 1]);
                    #pragma unroll
                    for (unsigned r = 0; r < 4; r++)
                        st_async_b64(mapa_u32(la, r), pv, mapa_u32(lm, r));
                }
            }
        }
    }
    CLUSTER_SYNC();
}

// =====================================================================
// rec2 (FUSED): layer-2 LSTM (hidden 256) incl. its own x-projection
// from g_comb + Wih_l. Single cluster of 8 CTAs, 256 threads.
// =====================================================================
__global__ void __cluster_dims__(8, 1, 1) __launch_bounds__(256, 1)
rec2_kernel(const float* __restrict__ Wih_l, const float* __restrict__ Whh_l,
            const float* __restrict__ bih_l, const float* __restrict__ bhh_l,
            const float* __restrict__ h0l,   const float* __restrict__ c0l)
{
    const int K2 = 2 * H;                    // 256
    __shared__ float sxin[SEQ * 2 * H];      // staged comb
    __shared__ float sX[SEQ * 128];          // x-proj addends for own rows
    __shared__ __align__(16) float sh[2][2 * H];
    __shared__ float sg[128];
    __shared__ float sc[32];
    __shared__ __align__(8) unsigned long long mbar[2];

    const int tid = threadIdx.x;             // 256
    const unsigned s = ctarank();            // 0..7
    const int j0 = (int)s * 32;

    const int rr = tid >> 1;                           // local gate row 0..127
    const int kh = (tid & 1) * 128;                    // k half
    const int grow = ((rr >> 5) << 8) + j0 + (rr & 31);
    const float bias = bih_l[grow] + bhh_l[grow];

    // ---- prologue: stage comb, compute own-row x-projection ----
    for (int idx = tid; idx < SEQ * K2; idx += 256)
        sxin[idx] = (&g_comb[0][0])[idx];
    {
        unsigned long long wi[64];
        const ulonglong2* wg = reinterpret_cast<const ulonglong2*>(Wih_l + (long)grow * K2 + kh);
        #pragma unroll
        for (int i = 0; i < 32; i++) { ulonglong2 v = wg[i]; wi[2*i] = v.x; wi[2*i+1] = v.y; }
        __syncthreads();
        #pragma unroll 1
        for (int t = 0; t < SEQ; t++) {
            unsigned long long a0 = 0ull, a1 = 0ull, a2 = 0ull, a3 = 0ull;
            const float* xv = &sxin[t * K2 + kh];
            #pragma unroll
            for (int i = 0; i < 32; i++) {
                ulonglong2 h2 = *reinterpret_cast<const ulonglong2*>(xv + 4 * i);
                if (i & 1) { fma2(a2, wi[2*i], h2.x); fma2(a3, wi[2*i+1], h2.y); }
                else       { fma2(a0, wi[2*i], h2.x); fma2(a1, wi[2*i+1], h2.y); }
            }
            float part = sum2(a0) + sum2(a1) + sum2(a2) + sum2(a3);
            part += __shfl_xor_sync(0xffffffffu, part, 1);
            if (!(tid & 1)) sX[t * 128 + rr] = part + bias;
        }
    }

    // ---- Whh_l half row -> registers ----
    unsigned long long w[64];
    {
        const ulonglong2* wg = reinterpret_cast<const ulonglong2*>(Whh_l + (long)grow * K2 + kh);
        #pragma unroll
        for (int i = 0; i < 32; i++) { ulonglong2 v = wg[i]; w[2*i] = v.x; w[2*i+1] = v.y; }
    }
    if (tid < K2) sh[0][tid] = h0l[tid];
    if (tid < 32) sc[tid]    = c0l[j0 + tid];
    if (tid == 0) { mbar_init(smem_u32(&mbar[0]), 1); mbar_init(smem_u32(&mbar[1]), 1); }
    __syncthreads();
    CLUSTER_SYNC();

    int ph0 = 0, ph1 = 0;
    #pragma unroll 1
    for (int t = 0; t < SEQ; t++) {
        if (t > 0) {
            int b = t & 1;
            mbar_wait(smem_u32(&mbar[b]), b ? ph1 : ph0);
            if (b) ph1 ^= 1; else ph0 ^= 1;
        }
        if (tid == 0 && t + 1 < SEQ) mbar_expect(smem_u32(&mbar[(t+1) & 1]), 8 * 32 * 4);

        const float* hb = sh[t & 1];
        unsigned long long a0 = 0ull, a1 = 0ull, a2 = 0ull, a3 = 0ull;
        #pragma unroll
        for (int i = 0; i < 32; i++) {
            ulonglong2 h2 = *reinterpret_cast<const ulonglong2*>(&hb[kh + 4 * i]);
            if (i & 1) { fma2(a2, w[2*i], h2.x); fma2(a3, w[2*i+1], h2.y); }
            else       { fma2(a0, w[2*i], h2.x); fma2(a1, w[2*i+1], h2.y); }
        }
        float part = sum2(a0) + sum2(a1) + sum2(a2) + sum2(a3);
        part += __shfl_xor_sync(0xffffffffu, part, 1);
        if (!(tid & 1)) sg[rr] = part + sX[t * 128 + rr];
        __syncthreads();

        if (tid < 32) {
            float gi = sg[tid], gf = sg[32 + tid], gg = sg[64 + tid], go = sg[96 + tid];
            float c = sigm(gf) * sc[tid] + sigm(gi) * tanhf(gg);
            float h = sigm(go) * tanhf(c);
            sc[tid] = c;
            g_hl[t][j0 + tid] = h;
            if (t + 1 < SEQ) {
                float hn = __shfl_down_sync(0xffffffffu, h, 1);
                if (!(tid & 1)) {
                    unsigned long long pv;
                    asm("mov.b64 %0, {%1, %2};" : "=l"(pv) : "f"(h), "f"(hn));
                    unsigned la = smem_u32(&sh[(t+1) & 1][j0 + tid]);
                    unsigned lm = smem_u32(&mbar[(t+1) & 1]);
                    #pragma unroll
                    for (unsigned r = 0; r < 8; r++)
                        st_async_b64(mapa_u32(la, r), pv, mapa_u32(lm, r));
                }
            }
        }
    }
    CLUSTER_SYNC();
}

// =====================================================================
extern "C" void kernel_launch(void* const* d_in, const int* in_sizes, int n_in,
                              void* d_out, int out_size)
{
    const float* x     = (const float*)d_in[0];
    const float* h0f   = (const float*)d_in[1];
    const float* c0f   = (const float*)d_in[2];
    const float* h0b   = (const float*)d_in[3];
    const float* c0b   = (const float*)d_in[4];
    const float* h0l   = (const float*)d_in[5];
    const float* c0l   = (const float*)d_in[6];
    const float* Wih_f = (const float*)d_in[7];
    const float* Whh_f = (const float*)d_in[8];
    const float* bih_f = (const float*)d_in[9];
    const float* bhh_f = (const float*)d_in[10];
    const float* Wih_b = (const float*)d_in[11];
    const float* Whh_b = (const float*)d_in[12];
    const float* bih_b = (const float*)d_in[13];
    const float* bhh_b = (const float*)d_in[14];
    const float* Wih_l = (const float*)d_in[15];
    const float* Whh_l = (const float*)d_in[16];
    const float* bih_l = (const float*)d_in[17];
    const float* bhh_l = (const float*)d_in[18];
    const float* Wlin  = (const float*)d_in[19];
    const float* blin  = (const float*)d_in[20];
    float* out = (float*)d_out;

    const int smem_g256 = (2 * 128 * 68 + SEQ * 256) * 4;    // 90112
    cudaFuncSetAttribute(gemm_kernel<256>, cudaFuncAttributeMaxDynamicSharedMemorySize, smem_g256);

    // 1) layer-1 recurrences, x-projection fused (2 clusters of 4)
    rec1_kernel<<<8, 256>>>(x, Wih_f, Whh_f, bih_f, bhh_f,
                            Wih_b, Whh_b, bih_b, bhh_b,
                            h0f, c0f, h0b, c0b);
    // 2) layer-2 recurrence, x-projection fused (1 cluster of 8)
    rec2_kernel<<<8, 256>>>(Wih_l, Whh_l, bih_l, bhh_l, h0l, c0l);
    // 3) final linear head: [20,100000] = hl @ Wlin^T + blin
    gemm_kernel<256><<<(NC + 127) / 128, 128, smem_g256>>>(Wlin, blin, out, NC);
}

// round 16
// speedup vs baseline: 1.0378x; 1.0378x over previous
#include <cuda_runtime.h>
#include <math.h>

#define SEQ 20
#define H   128
#define NC  100000

// ---------------- device scratch (no allocations allowed) ----------------
__device__ float g_comb[SEQ][2*H];        // [fwd_h, bwd_h] from rec1
__device__ float g_hl[SEQ][2*H];          // layer-2 hidden states from rec2

// ---------------- helpers ----------------
__device__ __forceinline__ void fma2(unsigned long long& d,
                                     unsigned long long a, unsigned long long b) {
    asm("fma.rn.f32x2 %0, %1, %2, %0;" : "+l"(d) : "l"(a), "l"(b));
}
__device__ __forceinline__ float sum2(unsigned long long v) {
    float lo, hi;
    asm("mov.b64 {%0, %1}, %2;" : "=f"(lo), "=f"(hi) : "l"(v));
    return lo + hi;
}
__device__ __forceinline__ float sigm(float x) { return 1.0f / (1.0f + expf(-x)); }

__device__ __forceinline__ unsigned smem_u32(const void* p) {
    return (unsigned)__cvta_generic_to_shared(p);
}
__device__ __forceinline__ unsigned mapa_u32(unsigned addr, unsigned rank) {
    unsigned d;
    asm("mapa.shared::cluster.u32 %0, %1, %2;" : "=r"(d) : "r"(addr), "r"(rank));
    return d;
}
__device__ __forceinline__ unsigned ctarank() {
    unsigned r; asm("mov.u32 %0, %%cluster_ctarank;" : "=r"(r)); return r;
}
#define CLUSTER_SYNC() do { \
    asm volatile("barrier.cluster.arrive.aligned;" ::: "memory"); \
    asm volatile("barrier.cluster.wait.aligned;"   ::: "memory"); } while (0)

// ---- st.async + mbarrier tx sync ----
__device__ __forceinline__ void mbar_init(unsigned addr, unsigned count) {
    asm volatile("mbarrier.init.shared.b64 [%0], %1;" :: "r"(addr), "r"(count) : "memory");
}
__device__ __forceinline__ void mbar_expect(unsigned addr, unsigned bytes) {
    asm volatile("mbarrier.arrive.expect_tx.shared.b64 _, [%0], %1;"
                 :: "r"(addr), "r"(bytes) : "memory");
}
// CTA-scope acquire: data + mbarrier are in OUR smem (st.async completes with
// complete_tx on our barrier, same visibility contract as TMA-delivered data).
__device__ __forceinline__ void mbar_wait_cta(unsigned addr, unsigned parity) {
    asm volatile(
        "{\n\t"
        ".reg .pred P;\n\t"
        "LW%=:\n\t"
        "mbarrier.try_wait.parity.acquire.cta.shared::cta.b64 P, [%0], %1, 0x989680;\n\t"
        "@P bra LD%=;\n\t"
        "bra LW%=;\n\t"
        "LD%=:\n\t"
        "}"
        :: "r"(addr), "r"(parity) : "memory");
}
__device__ __forceinline__ void st_async_b64(unsigned raddr, unsigned long long v, unsigned rmbar) {
    asm volatile("st.async.shared::cluster.mbarrier::complete_tx::bytes.b64 [%0], %1, [%2];"
                 :: "r"(raddr), "l"(v), "r"(rmbar) : "memory");
}

__device__ __forceinline__ void cp16(unsigned dst, const float* src) {
    asm volatile("cp.async.cg.shared.global [%0], [%1], 16;" :: "r"(dst), "l"(src));
}
__device__ __forceinline__ void cp_commit() {
    asm volatile("cp.async.commit_group;" ::: "memory");
}
__device__ __forceinline__ void cp_wait1() {
    asm volatile("cp.async.wait_group 1;" ::: "memory");
}
__device__ __forceinline__ void cp_wait0() {
    asm volatile("cp.async.wait_group 0;" ::: "memory");
}

// =====================================================================
// gemm_kernel<K>: head GEMM (unchanged). out[t][n] = hl[t]·W[n] + b[n].
// =====================================================================
template<int K>
__device__ __forceinline__ void issue_chunk(unsigned bufu, const float* __restrict__ W,
                                            long nbase, int N, int ch, int tid) {
    #pragma unroll
    for (int i = 0; i < 16; i++) {
        int idx = i * 128 + tid;
        int r = idx >> 4, c4 = idx & 15;
        long n = nbase + r; if (n >= N) n = 0;
        cp16(bufu + (unsigned)(r * 68 + c4 * 4) * 4u,
             W + n * K + ch * 64 + c4 * 4);
    }
    cp_commit();
}

template<int K>
__global__ void gemm_kernel(const float* __restrict__ W,
                            const float* __restrict__ b1,
                            float* __restrict__ out,
                            int N)
{
    constexpr int NCH = K / 64;
    extern __shared__ float sm[];
    float* sB0 = sm;
    float* sB1 = sm + 128 * 68;
    float* sA  = sm + 2 * 128 * 68;

    const int tid = threadIdx.x;           // 128
    long nbase = (long)blockIdx.x * 128;

    unsigned b0u = smem_u32(sB0), b1u = smem_u32(sB1);
    issue_chunk<K>(b0u, W, nbase, N, 0, tid);
    if (NCH > 1) issue_chunk<K>(b1u, W, nbase, N, 1, tid);

    const float* A = &g_hl[0][0];
    for (int idx = tid; idx < SEQ * (K / 4); idx += 128)
        reinterpret_cast<float4*>(sA)[idx] = reinterpret_cast<const float4*>(A)[idx];

    const int lane = tid & 31;
    const int tg   = tid >> 5;
    const int t0   = tg * 5;

    unsigned long long acc[20];
    #pragma unroll
    for (int i = 0; i < 20; i++) acc[i] = 0ull;

    #pragma unroll 1
    for (int ch = 0; ch < NCH; ch++) {
        if (ch < NCH - 1) cp_wait1(); else cp_wait0();
        __syncthreads();
        const float* buf = (ch & 1) ? sB1 : sB0;

        #pragma unroll
        for (int k4 = 0; k4 < 16; k4++) {
            ulonglong2 w[4], a[5];
            #pragma unroll
            for (int i = 0; i < 4; i++)
                w[i] = *reinterpret_cast<const ulonglong2*>(&buf[(lane + 32 * i) * 68 + 4 * k4]);
            #pragma unroll
            for (int j = 0; j < 5; j++)
                a[j] = *reinterpret_cast<const ulonglong2*>(&sA[(t0 + j) * K + ch * 64 + 4 * k4]);
            #pragma unroll
            for (int i = 0; i < 4; i++)
                #pragma unroll
                for (int j = 0; j < 5; j++) {
                    fma2(acc[i * 5 + j], w[i].x, a[j].x);
                    fma2(acc[i * 5 + j], w[i].y, a[j].y);
                }
        }
        __syncthreads();
        if (ch + 2 < NCH)
            issue_chunk<K>((ch & 1) ? b1u : b0u, W, nbase, N, ch + 2, tid);
    }

    #pragma unroll
    for (int i = 0; i < 4; i++) {
        long n = nbase + lane + 32 * i;
        if (n < N) {
            float bias = b1[n];
            #pragma unroll
            for (int j = 0; j < 5; j++)
                out[(long)(t0 + j) * N + n] = sum2(acc[i * 5 + j]) + bias;
        }
    }
}

// =====================================================================
// rec1: layer-1 LSTM, 2 clusters of 4 (grid 8), 256 threads.
// Gate-per-thread layout: thread = (jj = tid>>3, g = (tid>>1)&3, kh = tid&1)
//   -> owns gate row g*H + j0 + jj, k-half kh (64 floats, in registers).
// Lane bits: 0=kh, 1..2=g, 3..4=jj&3 -> shfl_xor(1)=kh reduce,
// shfl_xor(2)/(4)=gate allgather, shfl_down(8)=jj+1 (b64 pack).
// c replicated in registers of all 8 sibling threads. One __syncthreads
// per step (closes the double-buffer reuse window); mbar wait at cta scope.
// =====================================================================
__global__ void __cluster_dims__(4, 1, 1) __launch_bounds__(256, 1)
rec1_kernel(const float* __restrict__ x,
            const float* __restrict__ Wih_f, const float* __restrict__ Whh_f,
            const float* __restrict__ bih_f, const float* __restrict__ bhh_f,
            const float* __restrict__ Wih_b, const float* __restrict__ Whh_b,
            const float* __restrict__ bih_b, const float* __restrict__ bhh_b,
            const float* __restrict__ h0f, const float* __restrict__ c0f,
            const float* __restrict__ h0b, const float* __restrict__ c0b)
{
    __shared__ __align__(16) float sxin[SEQ * H];   // staged x (rev for bwd)
    __shared__ float sXr[SEQ * 256];                // per-thread X addend
    __shared__ __align__(16) float sh[2][H];
    __shared__ __align__(8) unsigned long long mbar[2];

    const int tid = threadIdx.x;             // 256
    const unsigned s = ctarank();            // 0..3
    const int d  = blockIdx.x >> 2;
    const int j0 = (int)s * 32;

    const float* Wih = d ? Wih_b : Wih_f;
    const float* Whh = d ? Whh_b : Whh_f;
    const float* bih = d ? bih_b : bih_f;
    const float* bhh = d ? bhh_b : bhh_f;
    const float* h0  = d ? h0b : h0f;
    const float* c0  = d ? c0b : c0f;

    const int jj = tid >> 3;
    const int g  = (tid >> 1) & 3;
    const int kh = tid & 1;
    const int row = g * H + j0 + jj;          // gate row within direction
    const float bias = bih[row] + bhh[row];

    // ---- stage x (t-reversed for bwd) ----
    for (int idx = tid; idx < SEQ * (H / 4); idx += 256) {
        int t = idx >> 5, k4 = idx & 31;
        reinterpret_cast<float4*>(sxin)[idx] =
            reinterpret_cast<const float4*>(x + (long)(d ? (SEQ - 1 - t) : t) * H)[k4];
    }
    __syncthreads();

    // ---- x-projection for own row: X[t] -> sXr ----
    {
        unsigned long long wi[32];
        const ulonglong2* wg = reinterpret_cast<const ulonglong2*>(Wih + (long)row * H + kh * 64);
        #pragma unroll
        for (int i = 0; i < 16; i++) { ulonglong2 v = wg[i]; wi[2*i] = v.x; wi[2*i+1] = v.y; }
        #pragma unroll 1
        for (int t = 0; t < SEQ; t++) {
            unsigned long long a0 = 0ull, a1 = 0ull;
            const float* xv = &sxin[t * H + kh * 64];
            #pragma unroll
            for (int i = 0; i < 16; i++) {
                ulonglong2 h2 = *reinterpret_cast<const ulonglong2*>(xv + 4 * i);
                fma2(a0, wi[2*i],   h2.x);
                fma2(a1, wi[2*i+1], h2.y);
            }
            float p = sum2(a0) + sum2(a1);
            p += __shfl_xor_sync(0xffffffffu, p, 1);        // kh reduce
            sXr[t * 256 + tid] = p + bias;
        }
    }

    // ---- Whh half-row -> registers ----
    unsigned long long w[32];
    {
        const ulonglong2* wg = reinterpret_cast<const ulonglong2*>(Whh + (long)row * H + kh * 64);
        #pragma unroll
        for (int i = 0; i < 16; i++) { ulonglong2 v = wg[i]; w[2*i] = v.x; w[2*i+1] = v.y; }
    }
    if (tid < H) sh[0][tid] = h0[tid];
    float c = c0[j0 + jj];                                   // replicated
    if (tid == 0) { mbar_init(smem_u32(&mbar[0]), 1); mbar_init(smem_u32(&mbar[1]), 1); }
    __syncthreads();
    CLUSTER_SYNC();                                          // mbar init visible

    int ph0 = 0, ph1 = 0;
    #pragma unroll 1
    for (int t = 0; t < SEQ; t++) {
        if (t > 0) {
            int b = t & 1;
            mbar_wait_cta(smem_u32(&mbar[b]), b ? ph1 : ph0);
            if (b) ph1 ^= 1; else ph0 ^= 1;
        }
        if (tid == 0 && t + 1 < SEQ) mbar_expect(smem_u32(&mbar[(t+1) & 1]), 4 * 32 * 4);

        // matvec over own half row
        const float* hb = &sh[t & 1][kh * 64];
        unsigned long long a0 = 0ull, a1 = 0ull;
        #pragma unroll
        for (int i = 0; i < 16; i++) {
            ulonglong2 h2 = *reinterpret_cast<const ulonglong2*>(hb + 4 * i);
            fma2(a0, w[2*i],   h2.x);
            fma2(a1, w[2*i+1], h2.y);
        }
        float dot = sum2(a0) + sum2(a1);
        __syncthreads();   // all sh[t&1] reads done before anyone triggers remote reuse

        dot += __shfl_xor_sync(0xffffffffu, dot, 1);         // kh reduce
        float gate = dot + sXr[t * 256 + tid];
        // gate allgather (butterfly over lane bits 1,2)
        float other = __shfl_xor_sync(0xffffffffu, gate, 2);
        float p0 = (g & 1) ? other : gate;
        float p1 = (g & 1) ? gate  : other;                  // (v_{2k}, v_{2k+1})
        float q0 = __shfl_xor_sync(0xffffffffu, p0, 4);
        float q1 = __shfl_xor_sync(0xffffffffu, p1, 4);
        float gi, gf, gg_, go;
        if ((g >> 1) == 0) { gi = p0; gf = p1; gg_ = q0; go = q1; }
        else               { gi = q0; gf = q1; gg_ = p0; go = p1; }

        c = sigm(gf) * c + sigm(gi) * tanhf(gg_);
        float h = sigm(go) * tanhf(c);

        if (g == 0 && kh == 0) g_comb[t][d * H + j0 + jj] = h;   // bwd in scan order
        float hn = __shfl_down_sync(0xffffffffu, h, 8);          // h(jj+1)
        if (t + 1 < SEQ && g == 0 && kh == 0 && !(jj & 1)) {
            unsigned long long pv;
            asm("mov.b64 %0, {%1, %2};" : "=l"(pv) : "f"(h), "f"(hn));
            unsigned la = smem_u32(&sh[(t+1) & 1][j0 + jj]);
            unsigned lm = smem_u32(&mbar[(t+1) & 1]);
            #pragma unroll
            for (unsigned r = 0; r < 4; r++)
                st_async_b64(mapa_u32(la, r), pv, mapa_u32(lm, r));
        }
    }
    CLUSTER_SYNC();
}

// =====================================================================
// rec2: layer-2 LSTM (hidden 256), 1 cluster of 8 (grid 8), 256 threads.
// Same gate-per-thread layout; k-half = 128 floats in registers.
// =====================================================================
__global__ void __cluster_dims__(8, 1, 1) __launch_bounds__(256, 1)
rec2_kernel(const float* __restrict__ Wih_l, const float* __restrict__ Whh_l,
            const float* __restrict__ bih_l, const float* __restrict__ bhh_l,
            const float* __restrict__ h0l,   const float* __restrict__ c0l)
{
    const int K2 = 2 * H;                     // 256
    __shared__ __align__(16) float sxin[SEQ * 2 * H];   // staged comb (40KB... 20KB)
    __shared__ float sXr[SEQ * 256];                    // per-thread X addend
    __shared__ __align__(16) float sh[2][2 * H];
    __shared__ __align__(8) unsigned long long mbar[2];

    const int tid = threadIdx.x;              // 256
    const unsigned s = ctarank();             // 0..7
    const int j0 = (int)s * 32;

    const int jj = tid >> 3;
    const int g  = (tid >> 1) & 3;
    const int kh = tid & 1;
    const int row = g * K2 + j0 + jj;         // gate row (of 8H)
    const float bias = bih_l[row] + bhh_l[row];

    // ---- stage comb ----
    for (int idx = tid; idx < SEQ * (K2 / 4); idx += 256)
        reinterpret_cast<float4*>(sxin)[idx] =
            reinterpret_cast<const float4*>(&g_comb[0][0])[idx];
    __syncthreads();

    // ---- x-projection for own row ----
    {
        unsigned long long wi[64];
        const ulonglong2* wg = reinterpret_cast<const ulonglong2*>(Wih_l + (long)row * K2 + kh * 128);
        #pragma unroll
        for (int i = 0; i < 32; i++) { ulonglong2 v = wg[i]; wi[2*i] = v.x; wi[2*i+1] = v.y; }
        #pragma unroll 1
        for (int t = 0; t < SEQ; t++) {
            unsigned long long a0 = 0ull, a1 = 0ull, a2 = 0ull, a3 = 0ull;
            const float* xv = &sxin[t * K2 + kh * 128];
            #pragma unroll
            for (int i = 0; i < 32; i++) {
                ulonglong2 h2 = *reinterpret_cast<const ulonglong2*>(xv + 4 * i);
                if (i & 1) { fma2(a2, wi[2*i], h2.x); fma2(a3, wi[2*i+1], h2.y); }
                else       { fma2(a0, wi[2*i], h2.x); fma2(a1, wi[2*i+1], h2.y); }
            }
            float p = sum2(a0) + sum2(a1) + sum2(a2) + sum2(a3);
            p += __shfl_xor_sync(0xffffffffu, p, 1);
            sXr[t * 256 + tid] = p + bias;
        }
    }

    // ---- Whh_l half-row -> registers ----
    unsigned long long w[64];
    {
        const ulonglong2* wg = reinterpret_cast<const ulonglong2*>(Whh_l + (long)row * K2 + kh * 128);
        #pragma unroll
        for (int i = 0; i < 32; i++) { ulonglong2 v = wg[i]; w[2*i] = v.x; w[2*i+1] = v.y; }
    }
    if (tid < K2) sh[0][tid] = h0l[tid];
    float c = c0l[j0 + jj];
    if (tid == 0) { mbar_init(smem_u32(&mbar[0]), 1); mbar_init(smem_u32(&mbar[1]), 1); }
    __syncthreads();
    CLUSTER_SYNC();

    int ph0 = 0, ph1 = 0;
    #pragma unroll 1
    for (int t = 0; t < SEQ; t++) {
        if (t > 0) {
            int b = t & 1;
            mbar_wait_cta(smem_u32(&mbar[b]), b ? ph1 : ph0);
            if (b) ph1 ^= 1; else ph0 ^= 1;
        }
        if (tid == 0 && t + 1 < SEQ) mbar_expect(smem_u32(&mbar[(t+1) & 1]), 8 * 32 * 4);

        const float* hb = &sh[t & 1][kh * 128];
        unsigned long long a0 = 0ull, a1 = 0ull, a2 = 0ull, a3 = 0ull;
        #pragma unroll
        for (int i = 0; i < 32; i++) {
            ulonglong2 h2 = *reinterpret_cast<const ulonglong2*>(hb + 4 * i);
            if (i & 1) { fma2(a2, w[2*i], h2.x); fma2(a3, w[2*i+1], h2.y); }
            else       { fma2(a0, w[2*i], h2.x); fma2(a1, w[2*i+1], h2.y); }
        }
        float dot = sum2(a0) + sum2(a1) + sum2(a2) + sum2(a3);
        __syncthreads();

        dot += __shfl_xor_sync(0xffffffffu, dot, 1);
        float gate = dot + sXr[t * 256 + tid];
        float other = __shfl_xor_sync(0xffffffffu, gate, 2);
        float p0 = (g & 1) ? other : gate;
        float p1 = (g & 1) ? gate  : other;
        float q0 = __shfl_xor_sync(0xffffffffu, p0, 4);
        float q1 = __shfl_xor_sync(0xffffffffu, p1, 4);
        float gi, gf, gg_, go;
        if ((g >> 1) == 0) { gi = p0; gf = p1; gg_ = q0; go = q1; }
        else               { gi = q0; gf = q1; gg_ = p0; go = p1; }

        c = sigm(gf) * c + sigm(gi) * tanhf(gg_);
        float h = sigm(go) * tanhf(c);

        if (g == 0 && kh == 0) g_hl[t][j0 + jj] = h;
        float hn = __shfl_down_sync(0xffffffffu, h, 8);
        if (t + 1 < SEQ && g == 0 && kh == 0 && !(jj & 1)) {
            unsigned long long pv;
            asm("mov.b64 %0, {%1, %2};" : "=l"(pv) : "f"(h), "f"(hn));
            unsigned la = smem_u32(&sh[(t+1) & 1][j0 + jj]);
            unsigned lm = smem_u32(&mbar[(t+1) & 1]);
            #pragma unroll
            for (unsigned r = 0; r < 8; r++)
                st_async_b64(mapa_u32(la, r), pv, mapa_u32(lm, r));
        }
    }
    CLUSTER_SYNC();
}

// =====================================================================
extern "C" void kernel_launch(void* const* d_in, const int* in_sizes, int n_in,
                              void* d_out, int out_size)
{
    const float* x     = (const float*)d_in[0];
    const float* h0f   = (const float*)d_in[1];
    const float* c0f   = (const float*)d_in[2];
    const float* h0b   = (const float*)d_in[3];
    const float* c0b   = (const float*)d_in[4];
    const float* h0l   = (const float*)d_in[5];
    const float* c0l   = (const float*)d_in[6];
    const float* Wih_f = (const float*)d_in[7];
    const float* Whh_f = (const float*)d_in[8];
    const float* bih_f = (const float*)d_in[9];
    const float* bhh_f = (const float*)d_in[10];
    const float* Wih_b = (const float*)d_in[11];
    const float* Whh_b = (const float*)d_in[12];
    const float* bih_b = (const float*)d_in[13];
    const float* bhh_b = (const float*)d_in[14];
    const float* Wih_l = (const float*)d_in[15];
    const float* Whh_l = (const float*)d_in[16];
    const float* bih_l = (const float*)d_in[17];
    const float* bhh_l = (const float*)d_in[18];
    const float* Wlin  = (const float*)d_in[19];
    const float* blin  = (const float*)d_in[20];
    float* out = (float*)d_out;

    const int smem_g256 = (2 * 128 * 68 + SEQ * 256) * 4;    // 90112
    cudaFuncSetAttribute(gemm_kernel<256>, cudaFuncAttributeMaxDynamicSharedMemorySize, smem_g256);

    // 1) layer-1 recurrences, x-projection fused (2 clusters of 4)
    rec1_kernel<<<8, 256>>>(x, Wih_f, Whh_f, bih_f, bhh_f,
                            Wih_b, Whh_b, bih_b, bhh_b,
                            h0f, c0f, h0b, c0b);
    // 2) layer-2 recurrence, x-projection fused (1 cluster of 8)
    rec2_kernel<<<8, 256>>>(Wih_l, Whh_l, bih_l, bhh_l, h0l, c0l);
    // 3) final linear head: [20,100000] = hl @ Wlin^T + blin
    gemm_kernel<256><<<(NC + 127) / 128, 128, smem_g256>>>(Wlin, blin, out, NC);
}